// round 9
// baseline (speedup 1.0000x reference)
#include <cuda_runtime.h>

// Problem constants (match reference)
#define BOX   120
#define VOL   (BOX * BOX * BOX)       // 1,728,000
#define NTYPE 11
#define BATCH 4
#define BT    (BATCH * NTYPE)         // 44
#define MAXA  512
#define NNB   2

#define YHALF      60                          // y-extent per CTA
#define PLANE_F    (YHALF * BOX)               // 7200 floats per half-plane
#define PLANE_F4   (PLANE_F / 4)               // 1800 float4
#define F4_PER_ROW (BOX / 4)                   // 30 float4 per z-row
#define KMAX       8                           // ceil(1800 / 256)
#define NBLOCKS    (BT * BOX * 2)              // 10560 CTAs

// ---------------------------------------------------------------------------
// num_atoms dtype sniff: values in [1,512]. If int64 (LE), 32-bit word 1 is
// the zero high half of element 0; if int32, word 1 is num_atoms[1] >= 1.
// ---------------------------------------------------------------------------
__device__ __forceinline__ int get_natoms(const int* __restrict__ p, int bt) {
    return (p[1] == 0) ? p[2 * bt] : p[bt];
}

__device__ __forceinline__ void stcs4(float4* addr, float4 v) {
    asm volatile("st.global.cs.v4.f32 [%0], {%1, %2, %3, %4};"
                 :: "l"(addr), "f"(v.x), "f"(v.y), "f"(v.z), "f"(v.w) : "memory");
}

// ---------------------------------------------------------------------------
// Fused kernel, register-tile version. One CTA per (bt, x, y-half). Each
// thread owns 8 float4s of the 60x120 tile in registers (f4 index
// tid + k*256 -> coalesced). Matched atoms (few) are gathered directly into
// those registers, then streamed to gmem once. No plane smem, no atomics.
// ---------------------------------------------------------------------------
__global__ void __launch_bounds__(256) fused_kernel(
    const float* __restrict__ coords,    // [BT, 3*MAXA]
    const int* __restrict__ num_atoms,   // [BT] int32 (or int64, sniffed)
    float* __restrict__ out)             // [BT, VOL]
{
    __shared__ int alist[MAXA];          // matched atom indices (2 KB)
    __shared__ int acnt;

    const int b  = blockIdx.x;
    const int h  = b & 1;                // y-half
    const int x  = (b >> 1) % BOX;
    const int bt = b / (BOX * 2);
    const int y0 = h * YHALF;
    const int tid = threadIdx.x;

    const int na = get_natoms(num_atoms, bt);
    const float* cbt = coords + (long long)bt * (3 * MAXA);

    if (tid == 0) acnt = 0;
    __syncthreads();

    // Scan atoms: does the atom's 5^3 stencil touch this (x, y-half) tile?
    for (int a = tid; a < na; a += 256) {
        const float ax = cbt[3 * a + 0];
        const float ay = cbt[3 * a + 1];
        const int cx = (int)floorf(ax);
        const int cy = (int)floorf(ay);
        const int ddx = x - cx;
        if (ddx >= -NNB && ddx <= NNB && cy >= y0 - NNB && cy <= y0 + YHALF - 1 + NNB) {
            alist[atomicAdd(&acnt, 1)] = a;
        }
    }
    __syncthreads();

    const int cnt = acnt;

    // Register tile: thread owns float4 f4idx = tid + k*256 (k < 8, f4 < 1800).
    float4 acc[KMAX];
    #pragma unroll
    for (int k = 0; k < KMAX; k++) acc[k] = make_float4(0.f, 0.f, 0.f, 0.f);

    const float fx = (float)x;
    for (int i = 0; i < cnt; i++) {
        const int a = alist[i];
        const float ax = cbt[3 * a + 0];   // same-address across warp -> broadcast
        const float ay = cbt[3 * a + 1];
        const float az = cbt[3 * a + 2];
        const int cy = (int)floorf(ay);
        const int cz = (int)floorf(az);
        const float dxv = fx - ax;
        const float dx2 = dxv * dxv;

        #pragma unroll
        for (int k = 0; k < KMAX; k++) {
            const int f4 = tid + k * 256;
            if (f4 >= PLANE_F4) break;
            const int iy = y0 + f4 / F4_PER_ROW;
            if (iy - cy < -NNB || iy - cy > NNB) continue;   // ~92% reject
            const int iz0 = (f4 % F4_PER_ROW) * 4;
            const float dyv = (float)iy - ay;
            const float rxy = dx2 + dyv * dyv;
            float* av = (float*)&acc[k];
            #pragma unroll
            for (int j = 0; j < 4; j++) {
                const int iz = iz0 + j;
                if (iz - cz >= -NNB && iz - cz <= NNB) {
                    const float dzv = (float)iz - az;
                    av[j] += __expf(-(rxy + dzv * dzv));
                }
            }
        }
    }

    // Coalesced streaming store of the tile (written exactly once).
    float4* dst = (float4*)(out + (long long)bt * VOL + x * (BOX * BOX) + y0 * BOX);
    #pragma unroll
    for (int k = 0; k < KMAX; k++) {
        const int f4 = tid + k * 256;
        if (f4 < PLANE_F4) stcs4(dst + f4, acc[k]);
    }
}

// ---------------------------------------------------------------------------
extern "C" void kernel_launch(void* const* d_in, const int* in_sizes, int n_in,
                              void* d_out, int out_size) {
    const float* coords    = (const float*)d_in[0];  // float32 [4,11,1536]
    const int*   num_atoms = (const int*)d_in[1];    // int32/int64 [4,11]
    float*       out       = (float*)d_out;          // float32 [4,11,120,120,120]

    fused_kernel<<<NBLOCKS, 256>>>(coords, num_atoms, out);
}

// round 10
// speedup vs baseline: 1.9048x; 1.9048x over previous
#include <cuda_runtime.h>

// Problem constants (match reference)
#define BOX   120
#define VOL   (BOX * BOX * BOX)       // 1,728,000
#define NTYPE 11
#define BATCH 4
#define BT    (BATCH * NTYPE)         // 44
#define MAXA  512
#define NNB   2

#define YHALF      60                          // y-extent per CTA
#define PLANE_F    (YHALF * BOX)               // 7200 floats per half-plane
#define PLANE_F4   (PLANE_F / 4)               // 1800 float4
#define F4_PER_ROW (BOX / 4)                   // 30 float4 per z-row
#define NBLOCKS    (BT * BOX * 2)              // 10560 CTAs

// ---------------------------------------------------------------------------
// num_atoms dtype sniff: values in [1,512]. If int64 (LE), 32-bit word 1 is
// the zero high half of element 0; if int32, word 1 is num_atoms[1] >= 1.
// ---------------------------------------------------------------------------
__device__ __forceinline__ int get_natoms(const int* __restrict__ p, int bt) {
    return (p[1] == 0) ? p[2 * bt] : p[bt];
}

__device__ __forceinline__ void stcs4(float4* addr, float4 v) {
    asm volatile("st.global.cs.v4.f32 [%0], {%1, %2, %3, %4};"
                 :: "l"(addr), "f"(v.x), "f"(v.y), "f"(v.z), "f"(v.w) : "memory");
}

// ---------------------------------------------------------------------------
// Fused kernel: one CTA per (bt, x, y-half). Builds its 60x120 tile in shared
// memory, but only for y-rows actually touched by an atom (tracked in a
// 2-word bitmask). Untouched rows never touch smem: zeroed rows stream from
// registers. Output written exactly once with streaming stores.
// ---------------------------------------------------------------------------
__global__ void __launch_bounds__(256) fused_kernel(
    const float* __restrict__ coords,    // [BT, 3*MAXA]
    const int* __restrict__ num_atoms,   // [BT] int32 (or int64, sniffed)
    float* __restrict__ out)             // [BT, VOL]
{
    __shared__ float plane[PLANE_F];         // 28.8 KB
    __shared__ int   alist[MAXA];            // matched atom indices
    __shared__ int   acnt;
    __shared__ unsigned rowmask[2];          // touched-row bits (60 rows)

    const int b  = blockIdx.x;
    const int h  = b & 1;                    // y-half
    const int x  = (b >> 1) % BOX;
    const int bt = b / (BOX * 2);
    const int y0 = h * YHALF;
    const int tid = threadIdx.x;

    const int na = get_natoms(num_atoms, bt);
    const float* cbt = coords + (long long)bt * (3 * MAXA);

    if (tid == 0) { acnt = 0; rowmask[0] = 0u; rowmask[1] = 0u; }
    __syncthreads();

    // Phase 1: scan atoms; collect those whose 5^3 stencil touches this tile,
    // and mark the y-rows they can write.
    for (int a = tid; a < na; a += 256) {
        const float ax = cbt[3 * a + 0];
        const float ay = cbt[3 * a + 1];
        const int cx = (int)floorf(ax);
        const int cy = (int)floorf(ay);
        const int ddx = x - cx;
        if (ddx >= -NNB && ddx <= NNB && cy >= y0 - NNB && cy <= y0 + YHALF - 1 + NNB) {
            alist[atomicAdd(&acnt, 1)] = a;
            const int rlo = max(cy - NNB - y0, 0);
            const int rhi = min(cy + NNB - y0, YHALF - 1);
            // Set bits [rlo, rhi] (at most 5 bits, may straddle the word split).
            for (int wdi = rlo >> 5; wdi <= (rhi >> 5); wdi++) {
                const int lo = max(rlo - wdi * 32, 0);
                const int hi = min(rhi - wdi * 32, 31);
                const unsigned bits = (hi - lo == 31) ? 0xFFFFFFFFu
                                    : (((1u << (hi - lo + 1)) - 1u) << lo);
                atomicOr(&rowmask[wdi], bits);
            }
        }
    }
    __syncthreads();

    const int cnt = acnt;
    float4* dst = (float4*)(out + (long long)bt * VOL + x * (BOX * BOX) + y0 * BOX);
    const float4 zero4 = make_float4(0.f, 0.f, 0.f, 0.f);
    float4* pl4 = (float4*)plane;

    if (cnt == 0) {
        // No atoms: stream zeros straight from registers.
        #pragma unroll
        for (int k = 0; k < 8; k++) {
            const int f4 = tid + k * 256;
            if (f4 < PLANE_F4) stcs4(dst + f4, zero4);
        }
        return;
    }

    const unsigned m0 = rowmask[0], m1 = rowmask[1];   // broadcast LDS, once

    // Phase 2: zero only the touched rows in smem.
    #pragma unroll
    for (int k = 0; k < 8; k++) {
        const int f4 = tid + k * 256;
        if (f4 < PLANE_F4) {
            const int r = f4 / F4_PER_ROW;
            const unsigned touched = (r < 32) ? (m0 >> r) : (m1 >> (r - 32));
            if (touched & 1u) pl4[f4] = zero4;
        }
    }
    __syncthreads();

    // Phase 3: scatter matched atoms into smem. Warp per atom; lane l < 25
    // owns cell (cy + l/5 - 2, cz + l%5 - 2).
    {
        const int wid  = tid >> 5;
        const int lane = tid & 31;
        const float fx = (float)x;
        for (int i = wid; i < cnt; i += 8) {
            const int a = alist[i];
            const float ax = cbt[3 * a + 0];
            const float ay = cbt[3 * a + 1];
            const float az = cbt[3 * a + 2];
            if (lane < 25) {
                const int cy = (int)floorf(ay);
                const int cz = (int)floorf(az);
                const int iy = cy + lane / 5 - NNB;
                const int iz = cz + lane % 5 - NNB;
                if (iy >= y0 && iy < y0 + YHALF && (unsigned)iz < BOX) {
                    const float dx = fx - ax;
                    const float dy = (float)iy - ay;
                    const float dz = (float)iz - az;
                    const float v = __expf(-(dx * dx + dy * dy + dz * dz));
                    atomicAdd(&plane[(iy - y0) * BOX + iz], v);
                }
            }
        }
    }
    __syncthreads();

    // Phase 4: stream the tile out. Touched rows from smem; others zeros.
    #pragma unroll
    for (int k = 0; k < 8; k++) {
        const int f4 = tid + k * 256;
        if (f4 < PLANE_F4) {
            const int r = f4 / F4_PER_ROW;
            const unsigned touched = (r < 32) ? (m0 >> r) : (m1 >> (r - 32));
            stcs4(dst + f4, (touched & 1u) ? pl4[f4] : zero4);
        }
    }
}

// ---------------------------------------------------------------------------
extern "C" void kernel_launch(void* const* d_in, const int* in_sizes, int n_in,
                              void* d_out, int out_size) {
    const float* coords    = (const float*)d_in[0];  // float32 [4,11,1536]
    const int*   num_atoms = (const int*)d_in[1];    // int32/int64 [4,11]
    float*       out       = (float*)d_out;          // float32 [4,11,120,120,120]

    fused_kernel<<<NBLOCKS, 256>>>(coords, num_atoms, out);
}